// round 9
// baseline (speedup 1.0000x reference)
#include <cuda_runtime.h>
#include <cstdint>

#define Bv 16
#define Tt 256
#define Nn 32
#define Ii 64
#define Hh 128
#define G4 512   // 4*H
#define CL 4     // cluster size (CTAs per n), each CTA owns 32 h

// Scratch: gates_x[t][b][n][g]
__device__ float g_gx[Tt * Bv * Nn * G4];   // 256 MiB

// ---------------------------------------------------------------------------
// Packed f32x2 helpers (sm_103a)
// ---------------------------------------------------------------------------
__device__ __forceinline__ unsigned long long pack2(float lo, float hi) {
    unsigned long long r;
    asm("mov.b64 %0, {%1, %2};" : "=l"(r)
        : "r"(__float_as_uint(lo)), "r"(__float_as_uint(hi)));
    return r;
}
__device__ __forceinline__ void unpack2(unsigned long long v, float& lo, float& hi) {
    unsigned a, b;
    asm("mov.b64 {%0, %1}, %2;" : "=r"(a), "=r"(b) : "l"(v));
    lo = __uint_as_float(a); hi = __uint_as_float(b);
}
__device__ __forceinline__ unsigned long long fma2(unsigned long long a,
                                                   unsigned long long b,
                                                   unsigned long long c) {
    unsigned long long d;
    asm("fma.rn.f32x2 %0, %1, %2, %3;" : "=l"(d) : "l"(a), "l"(b), "l"(c));
    return d;
}
__device__ __forceinline__ unsigned long long add2(unsigned long long a,
                                                   unsigned long long b) {
    unsigned long long d;
    asm("add.rn.f32x2 %0, %1, %2;" : "=l"(d) : "l"(a), "l"(b));
    return d;
}

__device__ __forceinline__ float fsig(float v) { return 1.f / (1.f + __expf(-v)); }
__device__ __forceinline__ float ftanh(float v) { return 1.f - 2.f / (__expf(2.f * v) + 1.f); }

// ---------------------------------------------------------------------------
// Kernel 1: gates_x (unchanged from R6 — passed, fma2-packed)
// ---------------------------------------------------------------------------
__global__ void __launch_bounds__(128) gates_x_kernel(
    const float* __restrict__ x,
    const float* __restrict__ W_ih,
    const float* __restrict__ b_ih,
    const float* __restrict__ b_hh)
{
    __shared__ __align__(16) float x_sm[64 * 68];  // [i][bt]
    __shared__ __align__(16) float w_sm[64 * 68];  // [i][g]

    const int n   = blockIdx.y;
    const int bt0 = blockIdx.x * 64;
    const int tid = threadIdx.x;

    for (int f = tid; f < 4096; f += 128) {
        const int bt = f >> 6, i = f & 63;
        x_sm[i * 68 + bt] = x[(size_t)(bt0 + bt) * (Nn * Ii) + n * Ii + i];
    }

    const float* Wn = W_ih + (size_t)n * G4 * Ii;
    const int btq = tid & 15;
    const int go  = tid >> 4;

    for (int g0 = 0; g0 < G4; g0 += 64) {
        __syncthreads();
        for (int f = tid; f < 4096; f += 128) {
            const int g = f >> 6, i = f & 63;
            w_sm[i * 68 + g] = Wn[(size_t)(g0 + g) * Ii + i];
        }
        __syncthreads();

        unsigned long long acc[4][4];
#pragma unroll
        for (int a = 0; a < 4; a++)
#pragma unroll
            for (int c = 0; c < 4; c++) acc[a][c] = 0ULL;

#pragma unroll 8
        for (int i = 0; i < 64; i++) {
            const float4 xv = *(const float4*)(x_sm + i * 68 + btq * 4);
            const ulonglong2 wA = *(const ulonglong2*)(w_sm + i * 68 + go * 8);
            const ulonglong2 wB = *(const ulonglong2*)(w_sm + i * 68 + go * 8 + 4);
            const unsigned long long xd0 = pack2(xv.x, xv.x);
            const unsigned long long xd1 = pack2(xv.y, xv.y);
            const unsigned long long xd2 = pack2(xv.z, xv.z);
            const unsigned long long xd3 = pack2(xv.w, xv.w);
            acc[0][0] = fma2(wA.x, xd0, acc[0][0]);
            acc[0][1] = fma2(wA.x, xd1, acc[0][1]);
            acc[0][2] = fma2(wA.x, xd2, acc[0][2]);
            acc[0][3] = fma2(wA.x, xd3, acc[0][3]);
            acc[1][0] = fma2(wA.y, xd0, acc[1][0]);
            acc[1][1] = fma2(wA.y, xd1, acc[1][1]);
            acc[1][2] = fma2(wA.y, xd2, acc[1][2]);
            acc[1][3] = fma2(wA.y, xd3, acc[1][3]);
            acc[2][0] = fma2(wB.x, xd0, acc[2][0]);
            acc[2][1] = fma2(wB.x, xd1, acc[2][1]);
            acc[2][2] = fma2(wB.x, xd2, acc[2][2]);
            acc[2][3] = fma2(wB.x, xd3, acc[2][3]);
            acc[3][0] = fma2(wB.y, xd0, acc[3][0]);
            acc[3][1] = fma2(wB.y, xd1, acc[3][1]);
            acc[3][2] = fma2(wB.y, xd2, acc[3][2]);
            acc[3][3] = fma2(wB.y, xd3, acc[3][3]);
        }

        unsigned long long bsp[4];
#pragma unroll
        for (int gp = 0; gp < 4; gp++) {
            const int g = g0 + go * 8 + gp * 2;
            const unsigned long long bi = *(const unsigned long long*)(b_ih + n * G4 + g);
            const unsigned long long bh = *(const unsigned long long*)(b_hh + n * G4 + g);
            bsp[gp] = add2(bi, bh);
        }
#pragma unroll
        for (int bb = 0; bb < 4; bb++) {
            const int bt = bt0 + btq * 4 + bb;
            const int b  = bt >> 8;
            const int t  = bt & 255;
            float* dst = g_gx + (((size_t)t * Bv + b) * Nn + n) * G4 + g0 + go * 8;
            ulonglong2 o0, o1;
            o0.x = add2(acc[0][bb], bsp[0]);
            o0.y = add2(acc[1][bb], bsp[1]);
            o1.x = add2(acc[2][bb], bsp[2]);
            o1.y = add2(acc[3][bb], bsp[3]);
            *(ulonglong2*)(dst)     = o0;
            *(ulonglong2*)(dst + 4) = o1;
        }
    }
}

// ---------------------------------------------------------------------------
// Kernel 2: persistent recurrence, CGA clusters, 256 threads/CTA.
// cluster = 4 CTAs per n (32 h each). grid = 128 CTAs.
// thread = (hq 0..15 -> 2 h packed, bq 0..15 -> 1 batch). c in registers.
// h_sm stores DUPLICATED pairs: h_sm[b][2k]=(h_k,h_k) so the consumer's packed
// operand is a single LDS.64. Double-buffered; exchange via DSMEM + split
// cluster barrier with gx(t+1) prefetch between arrive and wait.
// ---------------------------------------------------------------------------
#define WSTR        132                     // w k-stride (floats)
#define WSM_FLOATS  (128 * WSTR)            // 16896
#define HSTR        258                     // h row stride (floats): 128 dup pairs + pad
#define HSM_FLOATS  (Bv * HSTR)             // 4128 per buffer
#define RSMEM_BYTES ((WSM_FLOATS + 2 * HSM_FLOATS) * 4)

__global__ void __launch_bounds__(256, 1) __cluster_dims__(CL, 1, 1)
lstm_persistent(const float* __restrict__ W_hh,
                const float* __restrict__ h0,
                const float* __restrict__ c0,
                float* __restrict__ out,
                float* __restrict__ hn,
                float* __restrict__ cn)
{
    extern __shared__ __align__(16) float dsm[];
    float* w_sm = dsm;                  // [k][gpair][hq][g&1][h&1], k-stride WSTR
    float* h_sm = dsm + WSM_FLOATS;     // 2 x [b][2k] duplicated pairs

    const int tid = threadIdx.x;
    const int hq  = tid >> 4;           // 0..15 -> h pair
    const int bq  = tid & 15;           // 0..15 -> batch
    unsigned rank;
    asm("mov.u32 %0, %%cluster_ctarank;" : "=r"(rank));
    const int n      = blockIdx.x >> 2;
    const int h_base = (int)rank * 32;
    const int hh     = h_base + 2 * hq;

    // Peer SMEM base addresses of h_sm for all cluster ranks
    uint32_t h_sm_u32;
    asm("{ .reg .u64 t; cvta.to.shared.u64 t, %1; cvt.u32.u64 %0, t; }"
        : "=r"(h_sm_u32) : "l"((const void*)h_sm));
    uint32_t peer[CL];
#pragma unroll
    for (int r = 0; r < CL; r++)
        asm("mapa.shared::cluster.u32 %0, %1, %2;"
            : "=r"(peer[r]) : "r"(h_sm_u32), "r"((unsigned)r));

    // --- Load W_hh slice once, interleaved packed layout ---
    const float* Wn = W_hh + (size_t)n * G4 * Hh;
    for (int idx = tid; idx < 16384; idx += 256) {
        const int row = idx >> 7;            // g*32 + hl
        const int k   = idx & 127;
        const int g = row >> 5, hl = row & 31;
        w_sm[k * WSTR + (g >> 1) * 64 + (hl >> 1) * 4 + (g & 1) * 2 + (hl & 1)] =
            Wn[(size_t)(g * Hh + h_base + hl) * Hh + k];
    }

    // --- Initial h (duplicated) into buffer 0 ---
    for (int f = tid; f < Bv * Hh; f += 256) {
        const int b = f >> 7, k = f & 127;
        const float v = h0[(size_t)b * (Nn * Hh) + n * Hh + k];
        *(unsigned long long*)(h_sm + b * HSTR + 2 * k) = pack2(v, v);
    }

    // --- Cell state in registers (2 h for batch bq) ---
    float creg[2];
    creg[0] = c0[(size_t)bq * (Nn * Hh) + n * Hh + hh];
    creg[1] = c0[(size_t)bq * (Nn * Hh) + n * Hh + hh + 1];

    // --- Prefetch gates_x for t=0 ---
    float2 gx[4];
#pragma unroll
    for (int g = 0; g < 4; g++)
        gx[g] = *(const float2*)(g_gx + (((size_t)0 * Bv + bq) * Nn + n) * G4 + g * Hh + hh);

    __syncthreads();

    for (int t = 0; t < Tt; t++) {
        const float* cons = h_sm + (t & 1) * HSM_FLOATS;
        const uint32_t prodOff = (uint32_t)(((t + 1) & 1) * HSM_FLOATS * 4);

        // --- k-loop: 4 gate dot-products, packed over the h-pair ---
        unsigned long long acc[4];
        acc[0] = acc[1] = acc[2] = acc[3] = 0ULL;

        const float* cb = cons + bq * HSTR;
#pragma unroll 16
        for (int k = 0; k < 128; k++) {
            const ulonglong2 w01 = *(const ulonglong2*)(w_sm + k * WSTR + hq * 4);
            const ulonglong2 w23 = *(const ulonglong2*)(w_sm + k * WSTR + 64 + hq * 4);
            const unsigned long long hb = *(const unsigned long long*)(cb + 2 * k);
            acc[0] = fma2(w01.x, hb, acc[0]);
            acc[1] = fma2(w01.y, hb, acc[1]);
            acc[2] = fma2(w23.x, hb, acc[2]);
            acc[3] = fma2(w23.y, hb, acc[3]);
        }

        // --- Pointwise LSTM update (2 h for batch bq) ---
        float a[4][2];
#pragma unroll
        for (int g = 0; g < 4; g++) unpack2(acc[g], a[g][0], a[g][1]);

        float hnew[2];
#pragma unroll
        for (int h2 = 0; h2 < 2; h2++) {
            const float gi = a[0][h2] + (h2 ? gx[0].y : gx[0].x);
            const float gf = a[1][h2] + (h2 ? gx[1].y : gx[1].x);
            const float gg = a[2][h2] + (h2 ? gx[2].y : gx[2].x);
            const float go = a[3][h2] + (h2 ? gx[3].y : gx[3].x);
            const float cv = fsig(gf) * creg[h2] + fsig(gi) * ftanh(gg);
            hnew[h2] = fsig(go) * ftanh(cv);
            creg[h2] = cv;
        }

        if (t < Tt - 1) {
            // --- DSMEM: deliver duplicated h pairs to every cluster CTA ---
            const unsigned long long p0 = pack2(hnew[0], hnew[0]);
            const unsigned long long p1 = pack2(hnew[1], hnew[1]);
            const uint32_t off0 = prodOff + (uint32_t)((bq * HSTR + 2 * hh) * 4);
#pragma unroll
            for (int r = 0; r < CL; r++) {
                asm volatile("st.shared::cluster.b64 [%0], %1;"
                             :: "r"(peer[r] + off0), "l"(p0) : "memory");
                asm volatile("st.shared::cluster.b64 [%0], %1;"
                             :: "r"(peer[r] + off0 + 8), "l"(p1) : "memory");
            }
            asm volatile("barrier.cluster.arrive.aligned;" ::: "memory");

            // --- Hidden under barrier: out store + gx(t+1) prefetch ---
            *(float2*)(out + ((size_t)bq * Tt + t) * (Nn * Hh) + n * Hh + hh) =
                make_float2(hnew[0], hnew[1]);
#pragma unroll
            for (int g = 0; g < 4; g++)
                gx[g] = *(const float2*)(g_gx +
                    (((size_t)(t + 1) * Bv + bq) * Nn + n) * G4 + g * Hh + hh);

            asm volatile("barrier.cluster.wait.aligned;" ::: "memory");
        } else {
            *(float2*)(out + ((size_t)bq * Tt + t) * (Nn * Hh) + n * Hh + hh) =
                make_float2(hnew[0], hnew[1]);
            const size_t sidx = (size_t)bq * (Nn * Hh) + n * Hh + hh;
            *(float2*)(hn + sidx) = make_float2(hnew[0], hnew[1]);
            *(float2*)(cn + sidx) = make_float2(creg[0], creg[1]);
        }
    }

    // Keep cluster CTA lifetimes overlapped
    asm volatile("barrier.cluster.arrive.aligned;" ::: "memory");
    asm volatile("barrier.cluster.wait.aligned;"   ::: "memory");
}

// ---------------------------------------------------------------------------
extern "C" void kernel_launch(void* const* d_in, const int* in_sizes, int n_in,
                              void* d_out, int out_size)
{
    const float* x    = (const float*)d_in[0];
    const float* h0   = (const float*)d_in[1];
    const float* c0   = (const float*)d_in[2];
    const float* W_ih = (const float*)d_in[3];
    const float* W_hh = (const float*)d_in[4];
    const float* b_ih = (const float*)d_in[5];
    const float* b_hh = (const float*)d_in[6];

    float* out = (float*)d_out;                           // [B,T,N*H]
    float* hn  = out + (size_t)Bv * Tt * Nn * Hh;         // [1,B,N*H]
    float* cn  = hn + (size_t)Bv * Nn * Hh;               // [1,B,N*H]

    static bool attr_done = false;
    if (!attr_done) {
        cudaFuncSetAttribute(lstm_persistent,
                             cudaFuncAttributeMaxDynamicSharedMemorySize,
                             RSMEM_BYTES);
        attr_done = true;
    }

    gates_x_kernel<<<dim3(64, 32), 128>>>(x, W_ih, b_ih, b_hh);
    lstm_persistent<<<Nn * CL, 256, RSMEM_BYTES>>>(W_hh, h0, c0, out, hn, cn);
}

// round 11
// speedup vs baseline: 1.2286x; 1.2286x over previous
#include <cuda_runtime.h>
#include <cstdint>

#define Bv 16
#define Tt 256
#define Nn 32
#define Ii 64
#define Hh 128
#define G4 512   // 4*H
#define CL 4     // cluster size (CTAs per n), each CTA owns 32 h

// Scratch: gates_x[t][b][n][g]
__device__ float g_gx[Tt * Bv * Nn * G4];   // 256 MiB

// ---------------------------------------------------------------------------
// Packed f32x2 helpers (sm_103a)
// ---------------------------------------------------------------------------
__device__ __forceinline__ unsigned long long pack2(float lo, float hi) {
    unsigned long long r;
    asm("mov.b64 %0, {%1, %2};" : "=l"(r)
        : "r"(__float_as_uint(lo)), "r"(__float_as_uint(hi)));
    return r;
}
__device__ __forceinline__ void unpack2(unsigned long long v, float& lo, float& hi) {
    unsigned a, b;
    asm("mov.b64 {%0, %1}, %2;" : "=r"(a), "=r"(b) : "l"(v));
    lo = __uint_as_float(a); hi = __uint_as_float(b);
}
__device__ __forceinline__ unsigned long long fma2(unsigned long long a,
                                                   unsigned long long b,
                                                   unsigned long long c) {
    unsigned long long d;
    asm("fma.rn.f32x2 %0, %1, %2, %3;" : "=l"(d) : "l"(a), "l"(b), "l"(c));
    return d;
}
__device__ __forceinline__ unsigned long long add2(unsigned long long a,
                                                   unsigned long long b) {
    unsigned long long d;
    asm("add.rn.f32x2 %0, %1, %2;" : "=l"(d) : "l"(a), "l"(b));
    return d;
}

__device__ __forceinline__ float fsig(float v) { return 1.f / (1.f + __expf(-v)); }
__device__ __forceinline__ float ftanh(float v) { return 1.f - 2.f / (__expf(2.f * v) + 1.f); }

// ---------------------------------------------------------------------------
// Kernel 1: gates_x (unchanged — fma2-packed, passed since R6)
// ---------------------------------------------------------------------------
__global__ void __launch_bounds__(128) gates_x_kernel(
    const float* __restrict__ x,
    const float* __restrict__ W_ih,
    const float* __restrict__ b_ih,
    const float* __restrict__ b_hh)
{
    __shared__ __align__(16) float x_sm[64 * 68];  // [i][bt]
    __shared__ __align__(16) float w_sm[64 * 68];  // [i][g]

    const int n   = blockIdx.y;
    const int bt0 = blockIdx.x * 64;
    const int tid = threadIdx.x;

    for (int f = tid; f < 4096; f += 128) {
        const int bt = f >> 6, i = f & 63;
        x_sm[i * 68 + bt] = x[(size_t)(bt0 + bt) * (Nn * Ii) + n * Ii + i];
    }

    const float* Wn = W_ih + (size_t)n * G4 * Ii;
    const int btq = tid & 15;
    const int go  = tid >> 4;

    for (int g0 = 0; g0 < G4; g0 += 64) {
        __syncthreads();
        for (int f = tid; f < 4096; f += 128) {
            const int g = f >> 6, i = f & 63;
            w_sm[i * 68 + g] = Wn[(size_t)(g0 + g) * Ii + i];
        }
        __syncthreads();

        unsigned long long acc[4][4];
#pragma unroll
        for (int a = 0; a < 4; a++)
#pragma unroll
            for (int c = 0; c < 4; c++) acc[a][c] = 0ULL;

#pragma unroll 8
        for (int i = 0; i < 64; i++) {
            const float4 xv = *(const float4*)(x_sm + i * 68 + btq * 4);
            const ulonglong2 wA = *(const ulonglong2*)(w_sm + i * 68 + go * 8);
            const ulonglong2 wB = *(const ulonglong2*)(w_sm + i * 68 + go * 8 + 4);
            const unsigned long long xd0 = pack2(xv.x, xv.x);
            const unsigned long long xd1 = pack2(xv.y, xv.y);
            const unsigned long long xd2 = pack2(xv.z, xv.z);
            const unsigned long long xd3 = pack2(xv.w, xv.w);
            acc[0][0] = fma2(wA.x, xd0, acc[0][0]);
            acc[0][1] = fma2(wA.x, xd1, acc[0][1]);
            acc[0][2] = fma2(wA.x, xd2, acc[0][2]);
            acc[0][3] = fma2(wA.x, xd3, acc[0][3]);
            acc[1][0] = fma2(wA.y, xd0, acc[1][0]);
            acc[1][1] = fma2(wA.y, xd1, acc[1][1]);
            acc[1][2] = fma2(wA.y, xd2, acc[1][2]);
            acc[1][3] = fma2(wA.y, xd3, acc[1][3]);
            acc[2][0] = fma2(wB.x, xd0, acc[2][0]);
            acc[2][1] = fma2(wB.x, xd1, acc[2][1]);
            acc[2][2] = fma2(wB.x, xd2, acc[2][2]);
            acc[2][3] = fma2(wB.x, xd3, acc[2][3]);
            acc[3][0] = fma2(wB.y, xd0, acc[3][0]);
            acc[3][1] = fma2(wB.y, xd1, acc[3][1]);
            acc[3][2] = fma2(wB.y, xd2, acc[3][2]);
            acc[3][3] = fma2(wB.y, xd3, acc[3][3]);
        }

        unsigned long long bsp[4];
#pragma unroll
        for (int gp = 0; gp < 4; gp++) {
            const int g = g0 + go * 8 + gp * 2;
            const unsigned long long bi = *(const unsigned long long*)(b_ih + n * G4 + g);
            const unsigned long long bh = *(const unsigned long long*)(b_hh + n * G4 + g);
            bsp[gp] = add2(bi, bh);
        }
#pragma unroll
        for (int bb = 0; bb < 4; bb++) {
            const int bt = bt0 + btq * 4 + bb;
            const int b  = bt >> 8;
            const int t  = bt & 255;
            float* dst = g_gx + (((size_t)t * Bv + b) * Nn + n) * G4 + g0 + go * 8;
            ulonglong2 o0, o1;
            o0.x = add2(acc[0][bb], bsp[0]);
            o0.y = add2(acc[1][bb], bsp[1]);
            o1.x = add2(acc[2][bb], bsp[2]);
            o1.y = add2(acc[3][bb], bsp[3]);
            *(ulonglong2*)(dst)     = o0;
            *(ulonglong2*)(dst + 4) = o1;
        }
    }
}

// ---------------------------------------------------------------------------
// Kernel 2: persistent recurrence, register-resident W, k-packed fma2.
// cluster = 4 CTAs per n (32 h each); grid = 128 CTAs x 128 threads.
// Compute role:  thread = (g = tid>>5, hl = tid&31): owns W row (g*128+h) in
//                64 u64 regs; computes gate-g pre-activation for all 16 batches
//                via broadcast LDS of h. Results transposed through gbuf.
// Pointwise role: thread = (wq = tid>>5 -> batches 4wq..4wq+3, hl): c in regs,
//                activations, out-store, DSMEM h broadcast to cluster peers.
// ---------------------------------------------------------------------------
#define HBUF (Bv * Hh)          // one h buffer: 2048 floats

__global__ void __launch_bounds__(128, 1) __cluster_dims__(CL, 1, 1)
lstm_persistent(const float* __restrict__ W_hh,
                const float* __restrict__ h0,
                const float* __restrict__ c0,
                float* __restrict__ out,
                float* __restrict__ hn,
                float* __restrict__ cn)
{
    __shared__ __align__(16) float h_sm[2 * HBUF];       // [buf][b][k]
    __shared__ __align__(16) float gbuf[4 * Bv * 32];    // [g][b][hl]

    const int tid = threadIdx.x;
    const int g   = tid >> 5;          // compute role: gate
    const int wq  = tid >> 5;          // pointwise role: batch quad
    const int hl  = tid & 31;
    unsigned rank;
    asm("mov.u32 %0, %%cluster_ctarank;" : "=r"(rank));
    const int n      = blockIdx.x >> 2;
    const int h_base = (int)rank * 32;
    const int hg     = h_base + hl;    // global h within block n (0..127)

    // Peer SMEM base addresses of h_sm for all cluster ranks
    uint32_t h_sm_u32;
    asm("{ .reg .u64 t; cvta.to.shared.u64 t, %1; cvt.u32.u64 %0, t; }"
        : "=r"(h_sm_u32) : "l"((const void*)h_sm));
    uint32_t peer[CL];
#pragma unroll
    for (int r = 0; r < CL; r++)
        asm("mapa.shared::cluster.u32 %0, %1, %2;"
            : "=r"(peer[r]) : "r"(h_sm_u32), "r"((unsigned)r));

    // --- W row into registers, k-pairs packed: w[2i]=(W[4i?]..) pairs (k,k+1)
    unsigned long long w[64];
    {
        const float* wrow = W_hh + ((size_t)n * G4 + g * Hh + hg) * Hh;
#pragma unroll
        for (int i = 0; i < 32; i++) {
            const ulonglong2 v = *(const ulonglong2*)(wrow + i * 4);
            w[2 * i]     = v.x;
            w[2 * i + 1] = v.y;
        }
    }

    // --- Initial h into buffer 0 ---
    for (int f = tid; f < HBUF; f += 128) {
        const int b = f >> 7, k = f & 127;
        h_sm[b * Hh + k] = h0[(size_t)b * (Nn * Hh) + n * Hh + k];
    }

    // --- Cell state in registers (pointwise role: 4 batches at h = hg) ---
    float creg[4];
#pragma unroll
    for (int j = 0; j < 4; j++)
        creg[j] = c0[(size_t)(wq * 4 + j) * (Nn * Hh) + n * Hh + hg];

    __syncthreads();

    for (int t = 0; t < Tt; t++) {
        const float* cons = h_sm + (t & 1) * HBUF;
        const uint32_t prodOff = (uint32_t)(((t + 1) & 1) * HBUF * 4);

        // --- Prefetch gates_x for this step (pointwise role) ---
        float gxr[4][4];   // [gate][batch j]
#pragma unroll
        for (int gg = 0; gg < 4; gg++)
#pragma unroll
            for (int j = 0; j < 4; j++)
                gxr[gg][j] = g_gx[(((size_t)t * Bv + (wq * 4 + j)) * Nn + n) * G4
                                  + gg * Hh + hg];

        // --- k-loop: gate-g pre-activation for all 16 batches ---
        unsigned long long acc[16];
#pragma unroll
        for (int b = 0; b < 16; b++) acc[b] = 0ULL;

#pragma unroll
        for (int kq = 0; kq < 32; kq++) {          // 4 k per iter
            const unsigned long long w0 = w[2 * kq];
            const unsigned long long w1 = w[2 * kq + 1];
#pragma unroll
            for (int b = 0; b < 16; b++) {
                const ulonglong2 hv = *(const ulonglong2*)(cons + b * Hh + kq * 4);
                acc[b] = fma2(w0, hv.x, acc[b]);
                acc[b] = fma2(w1, hv.y, acc[b]);
            }
        }

        // --- Transpose through gbuf: gbuf[g][b][hl] ---
#pragma unroll
        for (int b = 0; b < 16; b++) {
            float lo, hi;
            unpack2(acc[b], lo, hi);
            gbuf[(g * Bv + b) * 32 + hl] = lo + hi;
        }
        __syncthreads();

        // --- Pointwise role: 4 batches at h = hg ---
        float hnew[4];
#pragma unroll
        for (int j = 0; j < 4; j++) {
            const int b = wq * 4 + j;
            const float gi = gbuf[(0 * Bv + b) * 32 + hl] + gxr[0][j];
            const float gf = gbuf[(1 * Bv + b) * 32 + hl] + gxr[1][j];
            const float gg = gbuf[(2 * Bv + b) * 32 + hl] + gxr[2][j];
            const float go = gbuf[(3 * Bv + b) * 32 + hl] + gxr[3][j];
            const float cv = fsig(gf) * creg[j] + fsig(gi) * ftanh(gg);
            hnew[j] = fsig(go) * ftanh(cv);
            creg[j] = cv;
        }

        if (t < Tt - 1) {
            // --- DSMEM: deliver h to every cluster CTA's next buffer ---
#pragma unroll
            for (int j = 0; j < 4; j++) {
                const uint32_t off = prodOff +
                    (uint32_t)(((wq * 4 + j) * Hh + hg) * 4);
                const uint32_t val = __float_as_uint(hnew[j]);
#pragma unroll
                for (int r = 0; r < CL; r++)
                    asm volatile("st.shared::cluster.b32 [%0], %1;"
                                 :: "r"(peer[r] + off), "r"(val) : "memory");
            }
            asm volatile("barrier.cluster.arrive.aligned;" ::: "memory");

            // --- Hidden under barrier: out store ---
#pragma unroll
            for (int j = 0; j < 4; j++)
                out[((size_t)(wq * 4 + j) * Tt + t) * (Nn * Hh) + n * Hh + hg] = hnew[j];

            asm volatile("barrier.cluster.wait.aligned;" ::: "memory");
        } else {
#pragma unroll
            for (int j = 0; j < 4; j++) {
                const int b = wq * 4 + j;
                out[((size_t)b * Tt + t) * (Nn * Hh) + n * Hh + hg] = hnew[j];
                const size_t sidx = (size_t)b * (Nn * Hh) + n * Hh + hg;
                hn[sidx] = hnew[j];
                cn[sidx] = creg[j];
            }
        }
    }

    // Keep cluster CTA lifetimes overlapped
    asm volatile("barrier.cluster.arrive.aligned;" ::: "memory");
    asm volatile("barrier.cluster.wait.aligned;"   ::: "memory");
}

// ---------------------------------------------------------------------------
extern "C" void kernel_launch(void* const* d_in, const int* in_sizes, int n_in,
                              void* d_out, int out_size)
{
    const float* x    = (const float*)d_in[0];
    const float* h0   = (const float*)d_in[1];
    const float* c0   = (const float*)d_in[2];
    const float* W_ih = (const float*)d_in[3];
    const float* W_hh = (const float*)d_in[4];
    const float* b_ih = (const float*)d_in[5];
    const float* b_hh = (const float*)d_in[6];

    float* out = (float*)d_out;                           // [B,T,N*H]
    float* hn  = out + (size_t)Bv * Tt * Nn * Hh;         // [1,B,N*H]
    float* cn  = hn + (size_t)Bv * Nn * Hh;               // [1,B,N*H]

    gates_x_kernel<<<dim3(64, 32), 128>>>(x, W_ih, b_ih, b_hh);
    lstm_persistent<<<Nn * CL, 128>>>(W_hh, h0, c0, out, hn, cn);
}

// round 14
// speedup vs baseline: 1.4463x; 1.1772x over previous
#include <cuda_runtime.h>
#include <cstdint>

#define Bv 16
#define Tt 256
#define Nn 32
#define Ii 64
#define Hh 128
#define G4 512   // 4*H
#define CL 4     // cluster size (CTAs per n), each CTA owns 32 h

// Scratch: gates_x[t][b][n][g]
__device__ float g_gx[Tt * Bv * Nn * G4];   // 256 MiB

// ---------------------------------------------------------------------------
// Packed f32x2 helpers (sm_103a)
// ---------------------------------------------------------------------------
__device__ __forceinline__ unsigned long long pack2(float lo, float hi) {
    unsigned long long r;
    asm("mov.b64 %0, {%1, %2};" : "=l"(r)
        : "r"(__float_as_uint(lo)), "r"(__float_as_uint(hi)));
    return r;
}
__device__ __forceinline__ void unpack2(unsigned long long v, float& lo, float& hi) {
    unsigned a, b;
    asm("mov.b64 {%0, %1}, %2;" : "=r"(a), "=r"(b) : "l"(v));
    lo = __uint_as_float(a); hi = __uint_as_float(b);
}
__device__ __forceinline__ unsigned long long fma2(unsigned long long a,
                                                   unsigned long long b,
                                                   unsigned long long c) {
    unsigned long long d;
    asm("fma.rn.f32x2 %0, %1, %2, %3;" : "=l"(d) : "l"(a), "l"(b), "l"(c));
    return d;
}
__device__ __forceinline__ unsigned long long add2(unsigned long long a,
                                                   unsigned long long b) {
    unsigned long long d;
    asm("add.rn.f32x2 %0, %1, %2;" : "=l"(d) : "l"(a), "l"(b));
    return d;
}

__device__ __forceinline__ float fsig(float v) { return 1.f / (1.f + __expf(-v)); }
__device__ __forceinline__ float ftanh(float v) { return 1.f - 2.f / (__expf(2.f * v) + 1.f); }

// ---------------------------------------------------------------------------
// Kernel 1: gates_x (unchanged — fma2-packed, passing since R6)
// ---------------------------------------------------------------------------
__global__ void __launch_bounds__(128) gates_x_kernel(
    const float* __restrict__ x,
    const float* __restrict__ W_ih,
    const float* __restrict__ b_ih,
    const float* __restrict__ b_hh)
{
    __shared__ __align__(16) float x_sm[64 * 68];  // [i][bt]
    __shared__ __align__(16) float w_sm[64 * 68];  // [i][g]

    const int n   = blockIdx.y;
    const int bt0 = blockIdx.x * 64;
    const int tid = threadIdx.x;

    for (int f = tid; f < 4096; f += 128) {
        const int bt = f >> 6, i = f & 63;
        x_sm[i * 68 + bt] = x[(size_t)(bt0 + bt) * (Nn * Ii) + n * Ii + i];
    }

    const float* Wn = W_ih + (size_t)n * G4 * Ii;
    const int btq = tid & 15;
    const int go  = tid >> 4;

    for (int g0 = 0; g0 < G4; g0 += 64) {
        __syncthreads();
        for (int f = tid; f < 4096; f += 128) {
            const int g = f >> 6, i = f & 63;
            w_sm[i * 68 + g] = Wn[(size_t)(g0 + g) * Ii + i];
        }
        __syncthreads();

        unsigned long long acc[4][4];
#pragma unroll
        for (int a = 0; a < 4; a++)
#pragma unroll
            for (int c = 0; c < 4; c++) acc[a][c] = 0ULL;

#pragma unroll 8
        for (int i = 0; i < 64; i++) {
            const float4 xv = *(const float4*)(x_sm + i * 68 + btq * 4);
            const ulonglong2 wA = *(const ulonglong2*)(w_sm + i * 68 + go * 8);
            const ulonglong2 wB = *(const ulonglong2*)(w_sm + i * 68 + go * 8 + 4);
            const unsigned long long xd0 = pack2(xv.x, xv.x);
            const unsigned long long xd1 = pack2(xv.y, xv.y);
            const unsigned long long xd2 = pack2(xv.z, xv.z);
            const unsigned long long xd3 = pack2(xv.w, xv.w);
            acc[0][0] = fma2(wA.x, xd0, acc[0][0]);
            acc[0][1] = fma2(wA.x, xd1, acc[0][1]);
            acc[0][2] = fma2(wA.x, xd2, acc[0][2]);
            acc[0][3] = fma2(wA.x, xd3, acc[0][3]);
            acc[1][0] = fma2(wA.y, xd0, acc[1][0]);
            acc[1][1] = fma2(wA.y, xd1, acc[1][1]);
            acc[1][2] = fma2(wA.y, xd2, acc[1][2]);
            acc[1][3] = fma2(wA.y, xd3, acc[1][3]);
            acc[2][0] = fma2(wB.x, xd0, acc[2][0]);
            acc[2][1] = fma2(wB.x, xd1, acc[2][1]);
            acc[2][2] = fma2(wB.x, xd2, acc[2][2]);
            acc[2][3] = fma2(wB.x, xd3, acc[2][3]);
            acc[3][0] = fma2(wB.y, xd0, acc[3][0]);
            acc[3][1] = fma2(wB.y, xd1, acc[3][1]);
            acc[3][2] = fma2(wB.y, xd2, acc[3][2]);
            acc[3][3] = fma2(wB.y, xd3, acc[3][3]);
        }

        unsigned long long bsp[4];
#pragma unroll
        for (int gp = 0; gp < 4; gp++) {
            const int g = g0 + go * 8 + gp * 2;
            const unsigned long long bi = *(const unsigned long long*)(b_ih + n * G4 + g);
            const unsigned long long bh = *(const unsigned long long*)(b_hh + n * G4 + g);
            bsp[gp] = add2(bi, bh);
        }
#pragma unroll
        for (int bb = 0; bb < 4; bb++) {
            const int bt = bt0 + btq * 4 + bb;
            const int b  = bt >> 8;
            const int t  = bt & 255;
            float* dst = g_gx + (((size_t)t * Bv + b) * Nn + n) * G4 + g0 + go * 8;
            ulonglong2 o0, o1;
            o0.x = add2(acc[0][bb], bsp[0]);
            o0.y = add2(acc[1][bb], bsp[1]);
            o1.x = add2(acc[2][bb], bsp[2]);
            o1.y = add2(acc[3][bb], bsp[3]);
            *(ulonglong2*)(dst)     = o0;
            *(ulonglong2*)(dst + 4) = o1;
        }
    }
}

// ---------------------------------------------------------------------------
// Kernel 2: persistent recurrence, register-resident W, k-packed fma2,
// 256 threads/CTA (2 warps/SMSP for latency hiding).
// cluster = 4 CTAs per n (32 h each); grid = 128 CTAs.
// Compute role:   tid = hb*128 + g*32 + hl. Thread owns W row (g, h_base+hl)
//                 in 64 u64 regs; computes gate-g pre-activation for 8 batches
//                 (hb*8..hb*8+7) via broadcast LDS of h. Transposed via gbuf.
// Pointwise role: tid = pw*32 + hl -> batches {2pw, 2pw+1} at h = h_base+hl.
//                 c in regs; DSMEM h broadcast to cluster peers.
// ---------------------------------------------------------------------------
#define HBUF (Bv * Hh)          // one h buffer: 2048 floats

__global__ void __launch_bounds__(256, 1) __cluster_dims__(CL, 1, 1)
lstm_persistent(const float* __restrict__ W_hh,
                const float* __restrict__ h0,
                const float* __restrict__ c0,
                float* __restrict__ out,
                float* __restrict__ hn,
                float* __restrict__ cn)
{
    __shared__ __align__(16) float h_sm[2 * HBUF];       // [buf][b][k]
    __shared__ __align__(16) float gbuf[4 * Bv * 32];    // [g][b][hl]

    const int tid = threadIdx.x;
    const int hb  = tid >> 7;          // compute role: batch half (0/1)
    const int g   = (tid >> 5) & 3;    // compute role: gate
    const int hl  = tid & 31;
    const int pw  = tid >> 5;          // pointwise role: 0..7 -> 2 batches
    unsigned rank;
    asm("mov.u32 %0, %%cluster_ctarank;" : "=r"(rank));
    const int n      = blockIdx.x >> 2;
    const int h_base = (int)rank * 32;
    const int hg     = h_base + hl;    // global h within block n (0..127)

    // Peer SMEM base addresses of h_sm for all cluster ranks
    uint32_t h_sm_u32;
    asm("{ .reg .u64 t; cvta.to.shared.u64 t, %1; cvt.u32.u64 %0, t; }"
        : "=r"(h_sm_u32) : "l"((const void*)h_sm));
    uint32_t peer[CL];
#pragma unroll
    for (int r = 0; r < CL; r++)
        asm("mapa.shared::cluster.u32 %0, %1, %2;"
            : "=r"(peer[r]) : "r"(h_sm_u32), "r"((unsigned)r));

    // --- W row into registers, k-pairs packed (same row in both halves) ---
    unsigned long long w[64];
    {
        const float* wrow = W_hh + ((size_t)n * G4 + g * Hh + hg) * Hh;
#pragma unroll
        for (int i = 0; i < 32; i++) {
            const ulonglong2 v = *(const ulonglong2*)(wrow + i * 4);
            w[2 * i]     = v.x;
            w[2 * i + 1] = v.y;
        }
    }

    // --- Initial h into buffer 0 ---
    for (int f = tid; f < HBUF; f += 256) {
        const int b = f >> 7, k = f & 127;
        h_sm[b * Hh + k] = h0[(size_t)b * (Nn * Hh) + n * Hh + k];
    }

    // --- Cell state in registers (pointwise role: 2 batches at h = hg) ---
    float creg[2];
#pragma unroll
    for (int j = 0; j < 2; j++)
        creg[j] = c0[(size_t)(pw * 2 + j) * (Nn * Hh) + n * Hh + hg];

    __syncthreads();

    for (int t = 0; t < Tt; t++) {
        const float* cons = h_sm + (t & 1) * HBUF;
        const uint32_t prodOff = (uint32_t)(((t + 1) & 1) * HBUF * 4);

        // --- Prefetch gates_x for this step (pointwise role; hidden by k-loop)
        float gxr[4][2];   // [gate][batch j]
#pragma unroll
        for (int gg = 0; gg < 4; gg++)
#pragma unroll
            for (int j = 0; j < 2; j++)
                gxr[gg][j] = g_gx[(((size_t)t * Bv + (pw * 2 + j)) * Nn + n) * G4
                                  + gg * Hh + hg];

        // --- k-loop: gate-g pre-activation for 8 batches (hb half) ---
        unsigned long long acc[8];
#pragma unroll
        for (int b = 0; b < 8; b++) acc[b] = 0ULL;

        const float* cbase = cons + hb * 8 * Hh;
#pragma unroll
        for (int kq = 0; kq < 32; kq++) {          // 4 k per iter
            const unsigned long long w0 = w[2 * kq];
            const unsigned long long w1 = w[2 * kq + 1];
#pragma unroll
            for (int b = 0; b < 8; b++) {
                const ulonglong2 hv = *(const ulonglong2*)(cbase + b * Hh + kq * 4);
                acc[b] = fma2(w0, hv.x, acc[b]);
                acc[b] = fma2(w1, hv.y, acc[b]);
            }
        }

        // --- Transpose through gbuf: gbuf[g][b][hl] ---
#pragma unroll
        for (int b = 0; b < 8; b++) {
            float lo, hi;
            unpack2(acc[b], lo, hi);
            gbuf[(g * Bv + hb * 8 + b) * 32 + hl] = lo + hi;
        }
        __syncthreads();

        // --- Pointwise role: 2 batches at h = hg ---
        float hnew[2];
#pragma unroll
        for (int j = 0; j < 2; j++) {
            const int b = pw * 2 + j;
            const float gi = gbuf[(0 * Bv + b) * 32 + hl] + gxr[0][j];
            const float gf = gbuf[(1 * Bv + b) * 32 + hl] + gxr[1][j];
            const float gg = gbuf[(2 * Bv + b) * 32 + hl] + gxr[2][j];
            const float go = gbuf[(3 * Bv + b) * 32 + hl] + gxr[3][j];
            const float cv = fsig(gf) * creg[j] + fsig(gi) * ftanh(gg);
            hnew[j] = fsig(go) * ftanh(cv);
            creg[j] = cv;
        }

        if (t < Tt - 1) {
            // --- DSMEM: deliver h to every cluster CTA's next buffer ---
#pragma unroll
            for (int j = 0; j < 2; j++) {
                const uint32_t off = prodOff +
                    (uint32_t)(((pw * 2 + j) * Hh + hg) * 4);
                const uint32_t val = __float_as_uint(hnew[j]);
#pragma unroll
                for (int r = 0; r < CL; r++)
                    asm volatile("st.shared::cluster.b32 [%0], %1;"
                                 :: "r"(peer[r] + off), "r"(val) : "memory");
            }
            asm volatile("barrier.cluster.arrive.aligned;" ::: "memory");

            // --- Hidden under barrier: out store ---
#pragma unroll
            for (int j = 0; j < 2; j++)
                out[((size_t)(pw * 2 + j) * Tt + t) * (Nn * Hh) + n * Hh + hg] = hnew[j];

            asm volatile("barrier.cluster.wait.aligned;" ::: "memory");
        } else {
#pragma unroll
            for (int j = 0; j < 2; j++) {
                const int b = pw * 2 + j;
                out[((size_t)b * Tt + t) * (Nn * Hh) + n * Hh + hg] = hnew[j];
                const size_t sidx = (size_t)b * (Nn * Hh) + n * Hh + hg;
                hn[sidx] = hnew[j];
                cn[sidx] = creg[j];
            }
        }
    }

    // Keep cluster CTA lifetimes overlapped
    asm volatile("barrier.cluster.arrive.aligned;" ::: "memory");
    asm volatile("barrier.cluster.wait.aligned;"   ::: "memory");
}

// ---------------------------------------------------------------------------
extern "C" void kernel_launch(void* const* d_in, const int* in_sizes, int n_in,
                              void* d_out, int out_size)
{
    const float* x    = (const float*)d_in[0];
    const float* h0   = (const float*)d_in[1];
    const float* c0   = (const float*)d_in[2];
    const float* W_ih = (const float*)d_in[3];
    const float* W_hh = (const float*)d_in[4];
    const float* b_ih = (const float*)d_in[5];
    const float* b_hh = (const float*)d_in[6];

    float* out = (float*)d_out;                           // [B,T,N*H]
    float* hn  = out + (size_t)Bv * Tt * Nn * Hh;         // [1,B,N*H]
    float* cn  = hn + (size_t)Bv * Nn * Hh;               // [1,B,N*H]

    gates_x_kernel<<<dim3(64, 32), 128>>>(x, W_ih, b_ih, b_hh);
    lstm_persistent<<<Nn * CL, 256>>>(W_hh, h0, c0, out, hn, cn);
}